// round 2
// baseline (speedup 1.0000x reference)
#include <cuda_runtime.h>

// ---------------- problem constants ----------------
#define DB 2
#define DS 2048
#define DD 512
#define DM 64
#define DT 2112              // DM + DS
#define DN 4224              // DB * DT
#define DH 8
#define DHD 64
#define DWIN 512
#define NSPLIT 8
#define SPLITROWS 528        // DN / NSPLIT
#define NLAY 2
#define LRC 1e-3f
#define WDC 1e-2f
#define EPSC 1e-8f
#define MAXALR 0.01f

typedef unsigned long long u64;

// packed f32x2 helpers (FFMA2 path — only reachable via PTX)
#define DUP2(d, v)   asm("mov.b64 %0, {%1, %1};" : "=l"(d) : "r"(__float_as_uint(v)))
#define PACK2(d, lo, hi) asm("mov.b64 %0, {%1, %2};" : "=l"(d) : "r"(__float_as_uint(lo)), "r"(__float_as_uint(hi)))
#define FFMA2(c, a, b)   asm("fma.rn.f32x2 %0, %1, %2, %0;" : "+l"(c) : "l"(a), "l"(b))
#define UNPK2(lo, hi, d) do { unsigned _ulo, _uhi; \
    asm("mov.b64 {%0, %1}, %2;" : "=r"(_ulo), "=r"(_uhi) : "l"(d)); \
    lo = __uint_as_float(_ulo); hi = __uint_as_float(_uhi); } while (0)

// ---------------- scratch (device globals; no allocs allowed) ----------------
static __device__ float g_XM[DN * DD];
static __device__ float g_K[DN * DD];
static __device__ float g_V[DN * DD];
static __device__ float g_Q[DN * DD];
static __device__ float g_LR[DN];
static __device__ float g_Z0[DN * DD];
static __device__ float g_X1[DN * DD];
static __device__ float g_Z1[DN * DD];
static __device__ float g_X2[DN * DD];
static __device__ float g_DY2[DN * DD];
static __device__ float g_DZ1[DN * DD];
static __device__ float g_DX1[DN * DD];
static __device__ float g_DZ0[DN * DD];
static __device__ float g_Wn[NLAY * DD * DD];
static __device__ float g_Y1[DN * DD];
static __device__ float g_Y2[DN * DD];
static __device__ float g_AQ[DN * DD];
static __device__ float g_AK[DN * DD];
static __device__ float g_AV[DN * DD];
static __device__ float g_AO[DN * DD];
static __device__ float g_S[DB * DH * DT * DWIN];               // banded scores/probs
static __device__ float g_GP[NLAY * NSPLIT * DD * DD];          // split-K grad partials

__device__ __forceinline__ float sigf(float z) { return 1.0f / (1.0f + __expf(-z)); }
__device__ __forceinline__ float silup(float z) {
    float s = sigf(z);
    return s * (1.0f + z * (1.0f - s));
}

// ================= 128x128x8 double-buffered f32x2 GEMM =================
// ORIENT 0 = NT : C = A @ W^T       (A [M,512], W [N,512], K contiguous in both)
// ORIENT 1 = NN : C = A @ W         (W [512,N])
// ORIENT 2 = TN : C = A^T @ W       (A,W [rows,512]; K = row index over a slice)
// EPI 0: Cz = acc
// EPI 1: Cz = acc ; Cx = A + silu(acc)
// EPI 2: Cx(d_out) = acc, rows mapped to (b, t>=DM)
// EPI 3: Cz = acc + R
template <int ORIENT, int EPI>
__device__ __forceinline__ void gemm_body(
    const float* __restrict__ A, const float* __restrict__ W,
    const float* __restrict__ R, float* __restrict__ Cz, float* __restrict__ Cx,
    int kbase) {
    __shared__ __align__(16) float As[2][8][128];
    __shared__ __align__(16) float Bs[2][8][128];
    const int tid = threadIdx.x;
    const int m0 = blockIdx.x << 7;
    const int n0 = blockIdx.y << 7;
    const int cx = tid & 15, cy = tid >> 4;

    u64 acc[8][4];
#pragma unroll
    for (int i = 0; i < 8; i++)
#pragma unroll
        for (int j = 0; j < 4; j++) acc[i][j] = 0ull;

    const int arow = tid >> 1, ac4 = (tid & 1) << 2;   // K-contig loads (128 rows x 8)
    const int kr = tid >> 5, kc4 = (tid & 31) << 2;    // K-major loads (8 rows x 128)

    const int NK = (ORIENT == 2 ? SPLITROWS / 8 : DD / 8);

    float4 sa, sb;
    // prologue: load tile kb=0
    {
        const int k0 = kbase;
        if (ORIENT == 2) {
            sa = *(const float4*)&A[(k0 + kr) * DD + m0 + kc4];
            sb = *(const float4*)&W[(k0 + kr) * DD + n0 + kc4];
        } else {
            sa = *(const float4*)&A[(m0 + arow) * DD + k0 + ac4];
            if (ORIENT == 0) sb = *(const float4*)&W[(n0 + arow) * DD + k0 + ac4];
            else             sb = *(const float4*)&W[(k0 + kr) * DD + n0 + kc4];
        }
    }
    // stage buf 0
    {
        if (ORIENT == 2) {
            *(float4*)&As[0][kr][kc4] = sa;
            *(float4*)&Bs[0][kr][kc4] = sb;
        } else {
            As[0][ac4 + 0][arow] = sa.x; As[0][ac4 + 1][arow] = sa.y;
            As[0][ac4 + 2][arow] = sa.z; As[0][ac4 + 3][arow] = sa.w;
            if (ORIENT == 0) {
                Bs[0][ac4 + 0][arow] = sb.x; Bs[0][ac4 + 1][arow] = sb.y;
                Bs[0][ac4 + 2][arow] = sb.z; Bs[0][ac4 + 3][arow] = sb.w;
            } else {
                *(float4*)&Bs[0][kr][kc4] = sb;
            }
        }
    }
    __syncthreads();

    for (int kb = 0; kb < NK; kb++) {
        const int buf = kb & 1;
        if (kb + 1 < NK) {
            const int k0 = kbase + ((kb + 1) << 3);
            if (ORIENT == 2) {
                sa = *(const float4*)&A[(k0 + kr) * DD + m0 + kc4];
                sb = *(const float4*)&W[(k0 + kr) * DD + n0 + kc4];
            } else {
                sa = *(const float4*)&A[(m0 + arow) * DD + k0 + ac4];
                if (ORIENT == 0) sb = *(const float4*)&W[(n0 + arow) * DD + k0 + ac4];
                else             sb = *(const float4*)&W[(k0 + kr) * DD + n0 + kc4];
            }
        }
#pragma unroll
        for (int kk = 0; kk < 8; kk++) {
            float4 a0 = *(const float4*)&As[buf][kk][cx << 2];
            float4 a1 = *(const float4*)&As[buf][kk][64 + (cx << 2)];
            float4 b0 = *(const float4*)&Bs[buf][kk][cy << 2];
            float4 b1 = *(const float4*)&Bs[buf][kk][64 + (cy << 2)];
            u64 bp0, bp1, bp2, bp3;
            PACK2(bp0, b0.x, b0.y); PACK2(bp1, b0.z, b0.w);
            PACK2(bp2, b1.x, b1.y); PACK2(bp3, b1.z, b1.w);
            float av[8] = {a0.x, a0.y, a0.z, a0.w, a1.x, a1.y, a1.z, a1.w};
#pragma unroll
            for (int i = 0; i < 8; i++) {
                u64 ad;
                DUP2(ad, av[i]);
                FFMA2(acc[i][0], ad, bp0);
                FFMA2(acc[i][1], ad, bp1);
                FFMA2(acc[i][2], ad, bp2);
                FFMA2(acc[i][3], ad, bp3);
            }
        }
        if (kb + 1 < NK) {
            const int nb = buf ^ 1;
            if (ORIENT == 2) {
                *(float4*)&As[nb][kr][kc4] = sa;
                *(float4*)&Bs[nb][kr][kc4] = sb;
            } else {
                As[nb][ac4 + 0][arow] = sa.x; As[nb][ac4 + 1][arow] = sa.y;
                As[nb][ac4 + 2][arow] = sa.z; As[nb][ac4 + 3][arow] = sa.w;
                if (ORIENT == 0) {
                    Bs[nb][ac4 + 0][arow] = sb.x; Bs[nb][ac4 + 1][arow] = sb.y;
                    Bs[nb][ac4 + 2][arow] = sb.z; Bs[nb][ac4 + 3][arow] = sb.w;
                } else {
                    *(float4*)&Bs[nb][kr][kc4] = sb;
                }
            }
        }
        __syncthreads();
    }

    // epilogue
#pragma unroll
    for (int ri = 0; ri < 8; ri++) {
        const int row = m0 + (cx << 2) + (ri & 3) + ((ri >> 2) << 6);
#pragma unroll
        for (int h = 0; h < 2; h++) {
            const int col = n0 + (cy << 2) + (h << 6);
            float4 z;
            UNPK2(z.x, z.y, acc[ri][2 * h]);
            UNPK2(z.z, z.w, acc[ri][2 * h + 1]);
            if (EPI == 0) {
                *(float4*)&Cz[row * DD + col] = z;
            } else if (EPI == 1) {
                *(float4*)&Cz[row * DD + col] = z;
                float4 a = *(const float4*)&A[row * DD + col];
                float4 o;
                o.x = a.x + z.x * sigf(z.x);
                o.y = a.y + z.y * sigf(z.y);
                o.z = a.z + z.z * sigf(z.z);
                o.w = a.w + z.w * sigf(z.w);
                *(float4*)&Cx[row * DD + col] = o;
            } else if (EPI == 3) {
                float4 r = *(const float4*)&R[row * DD + col];
                z.x += r.x; z.y += r.y; z.z += r.z; z.w += r.w;
                *(float4*)&Cz[row * DD + col] = z;
            } else {   // EPI 2: drop meta rows, write d_out
                const int bb = row / DT, t = row - bb * DT;
                if (t >= DM) *(float4*)&Cx[(bb * DS + (t - DM)) * DD + col] = z;
            }
        }
    }
}

template <int ORIENT, int EPI>
__global__ void __launch_bounds__(256, 1) gemm_k(
    const float* __restrict__ A, const float* __restrict__ W,
    const float* __restrict__ R, float* __restrict__ Cz, float* __restrict__ Cx) {
    if (ORIENT == 2) {
        const int sp = blockIdx.z;
        gemm_body<2, EPI>(A, W, R, Cz + sp * DD * DD, Cx, sp * SPLITROWS);
    } else {
        gemm_body<ORIENT, EPI>(A, W, R, Cz, Cx, 0);
    }
}

// batched NT projections: 3 weights, same A, z selects
__global__ void __launch_bounds__(256, 1) gemm_nt3_k(
    const float* __restrict__ A,
    const float* __restrict__ W0, const float* __restrict__ W1, const float* __restrict__ W2,
    float* __restrict__ C0, float* __restrict__ C1, float* __restrict__ C2) {
    const float* W = (blockIdx.z == 0) ? W0 : (blockIdx.z == 1 ? W1 : W2);
    float* C = (blockIdx.z == 0) ? C0 : (blockIdx.z == 1 ? C1 : C2);
    gemm_body<0, 0>(A, W, nullptr, C, nullptr, 0);
}

// ---------------- build xm = concat(meta, x) ----------------
__global__ void build_xm_k(const float* __restrict__ x, const float* __restrict__ meta,
                           float* __restrict__ XM) {
    int idx = blockIdx.x * blockDim.x + threadIdx.x;   // float4 index
    if (idx >= DN * DD / 4) return;
    int e = idx << 2;
    int n = e / DD, d = e - n * DD;
    int b = n / DT, t = n - b * DT;
    float4 v;
    if (t < DM) v = *(const float4*)&meta[t * DD + d];
    else        v = *(const float4*)&x[(b * DS + (t - DM)) * DD + d];
    *(float4*)&XM[e] = v;
}

// ---------------- adaptive lr: sigmoid(xm @ w_lr^T) * MAXALR ----------------
__global__ void lr_proj_k(const float* __restrict__ XM, const float* __restrict__ wlr,
                          float* __restrict__ out) {
    int warp = (blockIdx.x * blockDim.x + threadIdx.x) >> 5;
    int lane = threadIdx.x & 31;
    if (warp >= DN) return;
    const float* xr = XM + warp * DD;
    float s = 0.0f;
#pragma unroll
    for (int i = 0; i < DD / 32; i++) s = fmaf(xr[lane + i * 32], wlr[lane + i * 32], s);
#pragma unroll
    for (int o = 16; o > 0; o >>= 1) s += __shfl_xor_sync(0xffffffffu, s, o);
    if (lane == 0) out[warp] = MAXALR * sigf(s);
}

// ---------------- head gradient + layer1 activation backward (fused) ----------------
__global__ void grad_head_k(const float* __restrict__ X2, const float* __restrict__ Vv,
                            const float* __restrict__ Z1, const float* __restrict__ LRv,
                            float* __restrict__ DY2, float* __restrict__ DZ1) {
    int i = blockIdx.x * blockDim.x + threadIdx.x;
    if (i >= DN * DD) return;
    int n = i >> 9;
    float c = (2.0f / (float)DD) * LRv[n];
    float d2 = c * (X2[i] - Vv[i]);
    DY2[i] = d2;
    DZ1[i] = d2 * silup(Z1[i]);
}

__global__ void bwd_act0_k(const float* __restrict__ DX1, const float* __restrict__ Z0,
                           float* __restrict__ DZ0) {
    int i = blockIdx.x * blockDim.x + threadIdx.x;
    if (i >= DN * DD) return;
    DZ0[i] = DX1[i] * silup(Z0[i]);
}

// ---------------- reduce split-K partials + AdamW first step ----------------
__global__ void adamw_k(const float* __restrict__ W, float* __restrict__ Wn) {
    int idx = blockIdx.x * blockDim.x + threadIdx.x;
    if (idx >= NLAY * DD * DD) return;
    int l = idx / (DD * DD);
    int e = idx - l * (DD * DD);
    const float* gp = g_GP + l * NSPLIT * DD * DD;
    float g = 0.0f;
#pragma unroll
    for (int s = 0; s < NSPLIT; s++) g += gp[s * DD * DD + e];
    g *= (1.0f / 16.0f);
    float w = W[idx];
    Wn[idx] = w * (1.0f - LRC * WDC) - LRC * g / (fabsf(g) + EPSC);
}

#define FMA4x4(a, bb) do { \
    acc[0][0] = fmaf(a.x, bb.x, acc[0][0]); acc[0][1] = fmaf(a.x, bb.y, acc[0][1]); \
    acc[0][2] = fmaf(a.x, bb.z, acc[0][2]); acc[0][3] = fmaf(a.x, bb.w, acc[0][3]); \
    acc[1][0] = fmaf(a.y, bb.x, acc[1][0]); acc[1][1] = fmaf(a.y, bb.y, acc[1][1]); \
    acc[1][2] = fmaf(a.y, bb.z, acc[1][2]); acc[1][3] = fmaf(a.y, bb.w, acc[1][3]); \
    acc[2][0] = fmaf(a.z, bb.x, acc[2][0]); acc[2][1] = fmaf(a.z, bb.y, acc[2][1]); \
    acc[2][2] = fmaf(a.z, bb.z, acc[2][2]); acc[2][3] = fmaf(a.z, bb.w, acc[2][3]); \
    acc[3][0] = fmaf(a.w, bb.x, acc[3][0]); acc[3][1] = fmaf(a.w, bb.y, acc[3][1]); \
    acc[3][2] = fmaf(a.w, bb.z, acc[3][2]); acc[3][3] = fmaf(a.w, bb.w, acc[3][3]); \
} while (0)

// ---------------- attention: banded scores ----------------
__global__ void __launch_bounds__(256, 2) attn_scores_k(
    const float* __restrict__ AQ, const float* __restrict__ AK, float* __restrict__ Sb) {
    __shared__ __align__(16) float Qs[64][68];   // Qs[c][q]
    __shared__ __align__(16) float Ks[64][68];   // Ks[c][k]
    const int q0 = blockIdx.x << 6;
    const int h = blockIdx.y, b = blockIdx.z;
    const int tid = threadIdx.x;
    const int tx = tid & 15, ty = tid >> 4;
#pragma unroll
    for (int i = 0; i < 4; i++) {
        int idx = tid + (i << 8);                 // float4 index 0..1023
        int r = idx >> 4, c4 = (idx & 15) << 2;
        float4 v = *(const float4*)&AQ[(b * DT + q0 + r) * DD + h * DHD + c4];
        Qs[c4 + 0][r] = v.x; Qs[c4 + 1][r] = v.y; Qs[c4 + 2][r] = v.z; Qs[c4 + 3][r] = v.w;
    }
    __syncthreads();
    int kLo = q0 - (DWIN - 1);
    if (kLo < 0) kLo = 0;
    kLo &= ~63;
    for (int k0 = kLo; k0 <= q0 + 63; k0 += 64) {
#pragma unroll
        for (int i = 0; i < 4; i++) {
            int idx = tid + (i << 8);
            int r = idx >> 4, c4 = (idx & 15) << 2;
            int k = k0 + r;
            float4 v = make_float4(0.f, 0.f, 0.f, 0.f);
            if (k < DT) v = *(const float4*)&AK[(b * DT + k) * DD + h * DHD + c4];
            Ks[c4 + 0][r] = v.x; Ks[c4 + 1][r] = v.y; Ks[c4 + 2][r] = v.z; Ks[c4 + 3][r] = v.w;
        }
        __syncthreads();
        float acc[4][4] = {};
#pragma unroll 16
        for (int cc = 0; cc < 64; cc++) {
            float4 a = *(const float4*)&Qs[cc][tx << 2];
            float4 bb = *(const float4*)&Ks[cc][ty << 2];
            FMA4x4(a, bb);
        }
#pragma unroll
        for (int i = 0; i < 4; i++)
#pragma unroll
            for (int j = 0; j < 4; j++) {
                int q = q0 + (tx << 2) + i;
                int k = k0 + (ty << 2) + j;
                if (k <= q && q - k < DWIN)
                    Sb[((b * DH + h) * DT + q) * DWIN + (k - q + DWIN - 1)] = acc[i][j] * 0.125f;
            }
        __syncthreads();
    }
}

// ---------------- attention: softmax over band (warp per row) ----------------
__global__ void attn_softmax_k(float* __restrict__ Sb) {
    int gw = (blockIdx.x * blockDim.x + threadIdx.x) >> 5;
    int lane = threadIdx.x & 31;
    if (gw >= DB * DH * DT) return;
    int q = gw % DT;
    int wlo = DWIN - 1 - q;
    if (wlo < 0) wlo = 0;
    float* row = Sb + gw * DWIN;
    float v[16];
    float m = -1e30f;
#pragma unroll
    for (int i = 0; i < 16; i++) {
        int w = lane + i * 32;
        v[i] = (w >= wlo) ? row[w] : -1e30f;
        m = fmaxf(m, v[i]);
    }
#pragma unroll
    for (int o = 16; o > 0; o >>= 1) m = fmaxf(m, __shfl_xor_sync(0xffffffffu, m, o));
    float sum = 0.0f;
#pragma unroll
    for (int i = 0; i < 16; i++) {
        int w = lane + i * 32;
        v[i] = (w >= wlo) ? __expf(v[i] - m) : 0.0f;
        sum += v[i];
    }
#pragma unroll
    for (int o = 16; o > 0; o >>= 1) sum += __shfl_xor_sync(0xffffffffu, sum, o);
    float inv = 1.0f / sum;
#pragma unroll
    for (int i = 0; i < 16; i++) {
        int w = lane + i * 32;
        if (w >= wlo) row[w] = v[i] * inv;
    }
}

// ---------------- attention: P @ V ----------------
__global__ void __launch_bounds__(256, 2) attn_pv_k(
    const float* __restrict__ Sb, const float* __restrict__ AV, float* __restrict__ AO) {
    __shared__ __align__(16) float Ps[64][68];   // Ps[k][q]
    __shared__ __align__(16) float Vs[64][68];   // Vs[k][c]
    const int q0 = blockIdx.x << 6;
    const int h = blockIdx.y, b = blockIdx.z;
    const int tid = threadIdx.x;
    const int tx = tid & 15, ty = tid >> 4;
    float acc[4][4] = {};
    int kLo = q0 - (DWIN - 1);
    if (kLo < 0) kLo = 0;
    kLo &= ~63;
    for (int k0 = kLo; k0 <= q0 + 63; k0 += 64) {
#pragma unroll
        for (int i = 0; i < 4; i++) {
            int idx = tid + (i << 8);
            int r = idx >> 4, c4 = (idx & 15) << 2;
            int k = k0 + r;
            float4 v = make_float4(0.f, 0.f, 0.f, 0.f);
            if (k < DT) v = *(const float4*)&AV[(b * DT + k) * DD + h * DHD + c4];
            *(float4*)&Vs[r][c4] = v;
        }
#pragma unroll
        for (int i = 0; i < 16; i++) {
            int lin = tid + (i << 8);              // 0..4095
            int qi = lin >> 6, kj = lin & 63;
            int q = q0 + qi, k = k0 + kj;
            float p = 0.0f;
            if (k <= q && q - k < DWIN)
                p = Sb[((b * DH + h) * DT + q) * DWIN + (k - q + DWIN - 1)];
            Ps[kj][qi] = p;
        }
        __syncthreads();
#pragma unroll 16
        for (int kk = 0; kk < 64; kk++) {
            float4 a = *(const float4*)&Ps[kk][tx << 2];
            float4 bb = *(const float4*)&Vs[kk][ty << 2];
            FMA4x4(a, bb);
        }
        __syncthreads();
    }
#pragma unroll
    for (int i = 0; i < 4; i++)
#pragma unroll
        for (int j = 0; j < 4; j++)
            AO[(b * DT + q0 + (tx << 2) + i) * DD + h * DHD + (ty << 2) + j] = acc[i][j];
}

// ---------------- host ----------------
extern "C" void kernel_launch(void* const* d_in, const int* in_sizes, int n_in,
                              void* d_out, int out_size) {
    const float* x      = (const float*)d_in[0];
    const float* meta   = (const float*)d_in[1];
    const float* lmm_w  = (const float*)d_in[2];
    const float* w_q    = (const float*)d_in[3];
    const float* w_k    = (const float*)d_in[4];
    const float* w_v    = (const float*)d_in[5];
    const float* w_lr   = (const float*)d_in[6];
    const float* swa_wq = (const float*)d_in[7];
    const float* swa_wk = (const float*)d_in[8];
    const float* swa_wv = (const float*)d_in[9];
    const float* swa_wo = (const float*)d_in[10];
    float* out = (float*)d_out;

    float *XM, *K, *V, *Q, *LR, *Z0, *X1, *Z1, *X2, *DY2, *DZ1, *DX1, *DZ0;
    float *Wn, *Y1, *Y2, *AQ, *AK, *AV, *AO, *Sb, *GP;
    cudaGetSymbolAddress((void**)&XM, g_XM);
    cudaGetSymbolAddress((void**)&K, g_K);
    cudaGetSymbolAddress((void**)&V, g_V);
    cudaGetSymbolAddress((void**)&Q, g_Q);
    cudaGetSymbolAddress((void**)&LR, g_LR);
    cudaGetSymbolAddress((void**)&Z0, g_Z0);
    cudaGetSymbolAddress((void**)&X1, g_X1);
    cudaGetSymbolAddress((void**)&Z1, g_Z1);
    cudaGetSymbolAddress((void**)&X2, g_X2);
    cudaGetSymbolAddress((void**)&DY2, g_DY2);
    cudaGetSymbolAddress((void**)&DZ1, g_DZ1);
    cudaGetSymbolAddress((void**)&DX1, g_DX1);
    cudaGetSymbolAddress((void**)&DZ0, g_DZ0);
    cudaGetSymbolAddress((void**)&Wn, g_Wn);
    cudaGetSymbolAddress((void**)&Y1, g_Y1);
    cudaGetSymbolAddress((void**)&Y2, g_Y2);
    cudaGetSymbolAddress((void**)&AQ, g_AQ);
    cudaGetSymbolAddress((void**)&AK, g_AK);
    cudaGetSymbolAddress((void**)&AV, g_AV);
    cudaGetSymbolAddress((void**)&AO, g_AO);
    cudaGetSymbolAddress((void**)&Sb, g_S);
    cudaGetSymbolAddress((void**)&GP, g_GP);

    const dim3 gG(DN / 128, DD / 128);          // 33 x 4
    const dim3 gG3(DN / 128, DD / 128, 3);      // batched projections
    const dim3 gTN(DD / 128, DD / 128, NSPLIT); // 4 x 4 x 8
    const dim3 gAT(DT / 64, DH, DB);            // 33 x 8 x 2
    const int EW = (DN * DD + 255) / 256;

    // 1. concat meta + x
    build_xm_k<<<(DN * DD / 4 + 255) / 256, 256>>>(x, meta, XM);
    // 2. projections (batched: K, V, Q in one launch)
    gemm_nt3_k<<<gG3, 256>>>(XM, w_k, w_v, w_q, K, V, Q);
    lr_proj_k<<<(DN * 32 + 255) / 256, 256>>>(XM, w_lr, LR);
    // 3. LMM forward on keys (save z for backward)
    gemm_k<0, 1><<<gG, 256>>>(K, lmm_w, nullptr, Z0, X1);
    gemm_k<0, 1><<<gG, 256>>>(X1, lmm_w + DD * DD, nullptr, Z1, X2);
    // 4. backward
    grad_head_k<<<EW, 256>>>(X2, V, Z1, LR, DY2, DZ1);
    gemm_k<2, 0><<<gTN, 256>>>(DZ1, X1, nullptr, GP + NSPLIT * DD * DD, nullptr); // dW1
    gemm_k<1, 3><<<gG, 256>>>(DZ1, lmm_w + DD * DD, DY2, DX1, nullptr);           // dx1
    bwd_act0_k<<<EW, 256>>>(DX1, Z0, DZ0);
    gemm_k<2, 0><<<gTN, 256>>>(DZ0, K, nullptr, GP, nullptr);                     // dW0
    // 5. AdamW first step
    adamw_k<<<(NLAY * DD * DD + 255) / 256, 256>>>(lmm_w, Wn);
    // 6. retrieval with updated weights (Z0/Z1 reused as scratch)
    gemm_k<0, 1><<<gG, 256>>>(Q, Wn, nullptr, Z0, Y1);
    gemm_k<0, 1><<<gG, 256>>>(Y1, Wn + DD * DD, nullptr, Z1, Y2);
    // 7. sliding-window attention (batched QKV projection)
    gemm_nt3_k<<<gG3, 256>>>(Y2, swa_wq, swa_wk, swa_wv, AQ, AK, AV);
    attn_scores_k<<<gAT, 256>>>(AQ, AK, Sb);
    attn_softmax_k<<<(DB * DH * DT * 32 + 255) / 256, 256>>>(Sb);
    attn_pv_k<<<gAT, 256>>>(Sb, AV, AO);
    // 8. output projection, dropping meta rows
    gemm_k<0, 2><<<gG, 256>>>(AO, swa_wo, nullptr, nullptr, out);
}

// round 3
// speedup vs baseline: 1.3466x; 1.3466x over previous
#include <cuda_runtime.h>

// ---------------- problem constants ----------------
#define DB 2
#define DS 2048
#define DD 512
#define DM 64
#define DT 2112              // DM + DS
#define DN 4224              // DB * DT
#define DH 8
#define DHD 64
#define DWIN 512
#define NSPLIT 8
#define SPLITROWS 528        // DN / NSPLIT
#define NLAY 2
#define LRC 1e-3f
#define WDC 1e-2f
#define EPSC 1e-8f
#define MAXALR 0.01f

typedef unsigned long long u64;

// packed f32x2 helpers (FFMA2 path — only reachable via PTX)
#define DUP2(d, v)   asm("mov.b64 %0, {%1, %1};" : "=l"(d) : "r"(__float_as_uint(v)))
#define FFMA2(c, a, b)   asm("fma.rn.f32x2 %0, %1, %2, %0;" : "+l"(c) : "l"(a), "l"(b))
#define UNPK2(lo, hi, d) do { unsigned _ulo, _uhi; \
    asm("mov.b64 {%0, %1}, %2;" : "=r"(_ulo), "=r"(_uhi) : "l"(d)); \
    lo = __uint_as_float(_ulo); hi = __uint_as_float(_uhi); } while (0)

// ---------------- scratch (device globals; no allocs allowed) ----------------
static __device__ float g_XM[DN * DD];
static __device__ float g_K[DN * DD];
static __device__ float g_V[DN * DD];
static __device__ float g_Q[DN * DD];
static __device__ float g_LR[DN];
static __device__ float g_Z0[DN * DD];
static __device__ float g_X1[DN * DD];
static __device__ float g_Z1[DN * DD];
static __device__ float g_X2[DN * DD];
static __device__ float g_DY2[DN * DD];
static __device__ float g_DZ1[DN * DD];
static __device__ float g_DX1[DN * DD];
static __device__ float g_DZ0[DN * DD];
static __device__ float g_Wn[NLAY * DD * DD];
static __device__ float g_Y1[DN * DD];
static __device__ float g_Y2[DN * DD];
static __device__ float g_AQ[DN * DD];
static __device__ float g_AK[DN * DD];
static __device__ float g_AV[DN * DD];
static __device__ float g_AO[DN * DD];
static __device__ float g_S[DB * DH * DT * DWIN];               // banded scores/probs
static __device__ float g_GP[NLAY * NSPLIT * DD * DD];          // split-K grad partials

__device__ __forceinline__ float sigf(float z) { return 1.0f / (1.0f + __expf(-z)); }
__device__ __forceinline__ float silup(float z) {
    float s = sigf(z);
    return s * (1.0f + z * (1.0f - s));
}

// ================= 64x128x8 double-buffered f32x2 GEMM, 128 threads =================
// ORIENT 0 = NT : C = A @ W^T   (A [M,512], W [N,512], K contiguous in both)
// ORIENT 1 = NN : C = A @ W     (W [512,N])
// ORIENT 2 = TN : C = A^T @ W   (A,W [rows,512]; K = row index over a slice)
// EPI 0: Cz = acc
// EPI 1: Cz = acc ; Cx = A + silu(acc)
// EPI 2: Cx(d_out) = acc, rows mapped to (b, t>=DM)
// EPI 3: Cz = acc + R
template <int ORIENT, int EPI>
__device__ __forceinline__ void gemm_body(
    const float* __restrict__ A, const float* __restrict__ W,
    const float* __restrict__ R, float* __restrict__ Cz, float* __restrict__ Cx,
    int kbase) {
    __shared__ __align__(16) float As[2][8][64];
    __shared__ __align__(16) float Bs[2][8][128];
    const int tid = threadIdx.x;
    const int m0 = blockIdx.x << 6;
    const int n0 = blockIdx.y << 7;
    const int tx = tid & 7;        // -> 8 M rows at tx*8
    const int ty = tid >> 3;       // -> 8 N cols at ty*8

    u64 acc[8][4];
#pragma unroll
    for (int i = 0; i < 8; i++)
#pragma unroll
        for (int j = 0; j < 4; j++) acc[i][j] = 0ull;

    // staging indices
    const int arow = tid >> 1, ac4 = (tid & 1) << 2;    // NT/NN A: 64 rows x 8k
    const int kr = tid >> 4, kc = (tid & 15);           // K-major tiles: 8 rows

    const int NK = (ORIENT == 2 ? SPLITROWS / 8 : DD / 8);

    float4 sa, sb0, sb1;
    // ---- prologue load (kb = 0)
    {
        const int k0 = kbase;
        if (ORIENT == 2) {
            sa = *(const float4*)&A[(k0 + kr) * DD + m0 + (kc << 2)];
            sb0 = *(const float4*)&W[(k0 + kr) * DD + n0 + (kc << 3)];
            sb1 = *(const float4*)&W[(k0 + kr) * DD + n0 + (kc << 3) + 4];
        } else {
            sa = *(const float4*)&A[(m0 + arow) * DD + k0 + ac4];
            if (ORIENT == 0) {
                sb0 = *(const float4*)&W[(n0 + tid) * DD + k0];
                sb1 = *(const float4*)&W[(n0 + tid) * DD + k0 + 4];
            } else {
                sb0 = *(const float4*)&W[(k0 + kr) * DD + n0 + (kc << 3)];
                sb1 = *(const float4*)&W[(k0 + kr) * DD + n0 + (kc << 3) + 4];
            }
        }
    }
    // ---- stage buf 0
    {
        if (ORIENT == 2) {
            *(float4*)&As[0][kr][kc << 2] = sa;
            *(float4*)&Bs[0][kr][kc << 3] = sb0;
            *(float4*)&Bs[0][kr][(kc << 3) + 4] = sb1;
        } else {
            As[0][ac4 + 0][arow] = sa.x; As[0][ac4 + 1][arow] = sa.y;
            As[0][ac4 + 2][arow] = sa.z; As[0][ac4 + 3][arow] = sa.w;
            if (ORIENT == 0) {
                Bs[0][0][tid] = sb0.x; Bs[0][1][tid] = sb0.y;
                Bs[0][2][tid] = sb0.z; Bs[0][3][tid] = sb0.w;
                Bs[0][4][tid] = sb1.x; Bs[0][5][tid] = sb1.y;
                Bs[0][6][tid] = sb1.z; Bs[0][7][tid] = sb1.w;
            } else {
                *(float4*)&Bs[0][kr][kc << 3] = sb0;
                *(float4*)&Bs[0][kr][(kc << 3) + 4] = sb1;
            }
        }
    }
    __syncthreads();

    for (int kb = 0; kb < NK; kb++) {
        const int buf = kb & 1;
        if (kb + 1 < NK) {
            const int k0 = kbase + ((kb + 1) << 3);
            if (ORIENT == 2) {
                sa = *(const float4*)&A[(k0 + kr) * DD + m0 + (kc << 2)];
                sb0 = *(const float4*)&W[(k0 + kr) * DD + n0 + (kc << 3)];
                sb1 = *(const float4*)&W[(k0 + kr) * DD + n0 + (kc << 3) + 4];
            } else {
                sa = *(const float4*)&A[(m0 + arow) * DD + k0 + ac4];
                if (ORIENT == 0) {
                    sb0 = *(const float4*)&W[(n0 + tid) * DD + k0];
                    sb1 = *(const float4*)&W[(n0 + tid) * DD + k0 + 4];
                } else {
                    sb0 = *(const float4*)&W[(k0 + kr) * DD + n0 + (kc << 3)];
                    sb1 = *(const float4*)&W[(k0 + kr) * DD + n0 + (kc << 3) + 4];
                }
            }
        }
#pragma unroll
        for (int kk = 0; kk < 8; kk++) {
            float4 a0 = *(const float4*)&As[buf][kk][tx << 3];
            float4 a1 = *(const float4*)&As[buf][kk][(tx << 3) + 4];
            ulonglong2 bA = *(const ulonglong2*)&Bs[buf][kk][ty << 3];
            ulonglong2 bB = *(const ulonglong2*)&Bs[buf][kk][(ty << 3) + 4];
            float av[8] = {a0.x, a0.y, a0.z, a0.w, a1.x, a1.y, a1.z, a1.w};
#pragma unroll
            for (int i = 0; i < 8; i++) {
                u64 ad;
                DUP2(ad, av[i]);
                FFMA2(acc[i][0], ad, bA.x);
                FFMA2(acc[i][1], ad, bA.y);
                FFMA2(acc[i][2], ad, bB.x);
                FFMA2(acc[i][3], ad, bB.y);
            }
        }
        if (kb + 1 < NK) {
            const int nb = buf ^ 1;
            if (ORIENT == 2) {
                *(float4*)&As[nb][kr][kc << 2] = sa;
                *(float4*)&Bs[nb][kr][kc << 3] = sb0;
                *(float4*)&Bs[nb][kr][(kc << 3) + 4] = sb1;
            } else {
                As[nb][ac4 + 0][arow] = sa.x; As[nb][ac4 + 1][arow] = sa.y;
                As[nb][ac4 + 2][arow] = sa.z; As[nb][ac4 + 3][arow] = sa.w;
                if (ORIENT == 0) {
                    Bs[nb][0][tid] = sb0.x; Bs[nb][1][tid] = sb0.y;
                    Bs[nb][2][tid] = sb0.z; Bs[nb][3][tid] = sb0.w;
                    Bs[nb][4][tid] = sb1.x; Bs[nb][5][tid] = sb1.y;
                    Bs[nb][6][tid] = sb1.z; Bs[nb][7][tid] = sb1.w;
                } else {
                    *(float4*)&Bs[nb][kr][kc << 3] = sb0;
                    *(float4*)&Bs[nb][kr][(kc << 3) + 4] = sb1;
                }
            }
        }
        __syncthreads();
    }

    // ---- epilogue: 8 rows x 8 cols (two float4 per row)
#pragma unroll
    for (int i = 0; i < 8; i++) {
        const int row = m0 + (tx << 3) + i;
        const int col = n0 + (ty << 3);
        float4 z0, z1;
        UNPK2(z0.x, z0.y, acc[i][0]);
        UNPK2(z0.z, z0.w, acc[i][1]);
        UNPK2(z1.x, z1.y, acc[i][2]);
        UNPK2(z1.z, z1.w, acc[i][3]);
        if (EPI == 0) {
            *(float4*)&Cz[row * DD + col] = z0;
            *(float4*)&Cz[row * DD + col + 4] = z1;
        } else if (EPI == 1) {
            *(float4*)&Cz[row * DD + col] = z0;
            *(float4*)&Cz[row * DD + col + 4] = z1;
            float4 a0 = *(const float4*)&A[row * DD + col];
            float4 a1 = *(const float4*)&A[row * DD + col + 4];
            float4 o0, o1;
            o0.x = a0.x + z0.x * sigf(z0.x); o0.y = a0.y + z0.y * sigf(z0.y);
            o0.z = a0.z + z0.z * sigf(z0.z); o0.w = a0.w + z0.w * sigf(z0.w);
            o1.x = a1.x + z1.x * sigf(z1.x); o1.y = a1.y + z1.y * sigf(z1.y);
            o1.z = a1.z + z1.z * sigf(z1.z); o1.w = a1.w + z1.w * sigf(z1.w);
            *(float4*)&Cx[row * DD + col] = o0;
            *(float4*)&Cx[row * DD + col + 4] = o1;
        } else if (EPI == 3) {
            float4 r0 = *(const float4*)&R[row * DD + col];
            float4 r1 = *(const float4*)&R[row * DD + col + 4];
            z0.x += r0.x; z0.y += r0.y; z0.z += r0.z; z0.w += r0.w;
            z1.x += r1.x; z1.y += r1.y; z1.z += r1.z; z1.w += r1.w;
            *(float4*)&Cz[row * DD + col] = z0;
            *(float4*)&Cz[row * DD + col + 4] = z1;
        } else {   // EPI 2: drop meta rows, write d_out
            const int bb = row / DT, t = row - bb * DT;
            if (t >= DM) {
                *(float4*)&Cx[(bb * DS + (t - DM)) * DD + col] = z0;
                *(float4*)&Cx[(bb * DS + (t - DM)) * DD + col + 4] = z1;
            }
        }
    }
}

template <int ORIENT, int EPI>
__global__ void __launch_bounds__(128, 4) gemm_k(
    const float* __restrict__ A, const float* __restrict__ W,
    const float* __restrict__ R, float* __restrict__ Cz, float* __restrict__ Cx) {
    if (ORIENT == 2) {
        const int sp = blockIdx.z;
        gemm_body<2, EPI>(A, W, R, Cz + sp * DD * DD, Cx, sp * SPLITROWS);
    } else {
        gemm_body<ORIENT, EPI>(A, W, R, Cz, Cx, 0);
    }
}

// batched NT projections: 3 weights, same A, z selects
__global__ void __launch_bounds__(128, 4) gemm_nt3_k(
    const float* __restrict__ A,
    const float* __restrict__ W0, const float* __restrict__ W1, const float* __restrict__ W2,
    float* __restrict__ C0, float* __restrict__ C1, float* __restrict__ C2) {
    const float* W = (blockIdx.z == 0) ? W0 : (blockIdx.z == 1 ? W1 : W2);
    float* C = (blockIdx.z == 0) ? C0 : (blockIdx.z == 1 ? C1 : C2);
    gemm_body<0, 0>(A, W, nullptr, C, nullptr, 0);
}

// ---------------- build xm = concat(meta, x) ----------------
__global__ void build_xm_k(const float* __restrict__ x, const float* __restrict__ meta,
                           float* __restrict__ XM) {
    int idx = blockIdx.x * blockDim.x + threadIdx.x;   // float4 index
    if (idx >= DN * DD / 4) return;
    int e = idx << 2;
    int n = e / DD, d = e - n * DD;
    int b = n / DT, t = n - b * DT;
    float4 v;
    if (t < DM) v = *(const float4*)&meta[t * DD + d];
    else        v = *(const float4*)&x[(b * DS + (t - DM)) * DD + d];
    *(float4*)&XM[e] = v;
}

// ---------------- adaptive lr: sigmoid(xm @ w_lr^T) * MAXALR ----------------
__global__ void lr_proj_k(const float* __restrict__ XM, const float* __restrict__ wlr,
                          float* __restrict__ out) {
    int warp = (blockIdx.x * blockDim.x + threadIdx.x) >> 5;
    int lane = threadIdx.x & 31;
    if (warp >= DN) return;
    const float* xr = XM + warp * DD;
    float s = 0.0f;
#pragma unroll
    for (int i = 0; i < DD / 32; i++) s = fmaf(xr[lane + i * 32], wlr[lane + i * 32], s);
#pragma unroll
    for (int o = 16; o > 0; o >>= 1) s += __shfl_xor_sync(0xffffffffu, s, o);
    if (lane == 0) out[warp] = MAXALR * sigf(s);
}

// ---------------- head gradient + layer1 activation backward (fused) ----------------
__global__ void grad_head_k(const float* __restrict__ X2, const float* __restrict__ Vv,
                            const float* __restrict__ Z1, const float* __restrict__ LRv,
                            float* __restrict__ DY2, float* __restrict__ DZ1) {
    int i = blockIdx.x * blockDim.x + threadIdx.x;
    if (i >= DN * DD) return;
    int n = i >> 9;
    float c = (2.0f / (float)DD) * LRv[n];
    float d2 = c * (X2[i] - Vv[i]);
    DY2[i] = d2;
    DZ1[i] = d2 * silup(Z1[i]);
}

__global__ void bwd_act0_k(const float* __restrict__ DX1, const float* __restrict__ Z0,
                           float* __restrict__ DZ0) {
    int i = blockIdx.x * blockDim.x + threadIdx.x;
    if (i >= DN * DD) return;
    DZ0[i] = DX1[i] * silup(Z0[i]);
}

// ---------------- reduce split-K partials + AdamW first step ----------------
__global__ void adamw_k(const float* __restrict__ W, float* __restrict__ Wn) {
    int idx = blockIdx.x * blockDim.x + threadIdx.x;
    if (idx >= NLAY * DD * DD) return;
    int l = idx / (DD * DD);
    int e = idx - l * (DD * DD);
    const float* gp = g_GP + l * NSPLIT * DD * DD;
    float g = 0.0f;
#pragma unroll
    for (int s = 0; s < NSPLIT; s++) g += gp[s * DD * DD + e];
    g *= (1.0f / 16.0f);
    float w = W[idx];
    Wn[idx] = w * (1.0f - LRC * WDC) - LRC * g / (fabsf(g) + EPSC);
}

#define FMA4x4(a, bb) do { \
    acc[0][0] = fmaf(a.x, bb.x, acc[0][0]); acc[0][1] = fmaf(a.x, bb.y, acc[0][1]); \
    acc[0][2] = fmaf(a.x, bb.z, acc[0][2]); acc[0][3] = fmaf(a.x, bb.w, acc[0][3]); \
    acc[1][0] = fmaf(a.y, bb.x, acc[1][0]); acc[1][1] = fmaf(a.y, bb.y, acc[1][1]); \
    acc[1][2] = fmaf(a.y, bb.z, acc[1][2]); acc[1][3] = fmaf(a.y, bb.w, acc[1][3]); \
    acc[2][0] = fmaf(a.z, bb.x, acc[2][0]); acc[2][1] = fmaf(a.z, bb.y, acc[2][1]); \
    acc[2][2] = fmaf(a.z, bb.z, acc[2][2]); acc[2][3] = fmaf(a.z, bb.w, acc[2][3]); \
    acc[3][0] = fmaf(a.w, bb.x, acc[3][0]); acc[3][1] = fmaf(a.w, bb.y, acc[3][1]); \
    acc[3][2] = fmaf(a.w, bb.z, acc[3][2]); acc[3][3] = fmaf(a.w, bb.w, acc[3][3]); \
} while (0)

// ---------------- attention: banded scores ----------------
__global__ void __launch_bounds__(256, 2) attn_scores_k(
    const float* __restrict__ AQ, const float* __restrict__ AK, float* __restrict__ Sb) {
    __shared__ __align__(16) float Qs[64][68];   // Qs[c][q]
    __shared__ __align__(16) float Ks[64][68];   // Ks[c][k]
    const int q0 = blockIdx.x << 6;
    const int h = blockIdx.y, b = blockIdx.z;
    const int tid = threadIdx.x;
    const int tx = tid & 15, ty = tid >> 4;
#pragma unroll
    for (int i = 0; i < 4; i++) {
        int idx = tid + (i << 8);                 // float4 index 0..1023
        int r = idx >> 4, c4 = (idx & 15) << 2;
        float4 v = *(const float4*)&AQ[(b * DT + q0 + r) * DD + h * DHD + c4];
        Qs[c4 + 0][r] = v.x; Qs[c4 + 1][r] = v.y; Qs[c4 + 2][r] = v.z; Qs[c4 + 3][r] = v.w;
    }
    __syncthreads();
    int kLo = q0 - (DWIN - 1);
    if (kLo < 0) kLo = 0;
    kLo &= ~63;
    for (int k0 = kLo; k0 <= q0 + 63; k0 += 64) {
#pragma unroll
        for (int i = 0; i < 4; i++) {
            int idx = tid + (i << 8);
            int r = idx >> 4, c4 = (idx & 15) << 2;
            int k = k0 + r;
            float4 v = make_float4(0.f, 0.f, 0.f, 0.f);
            if (k < DT) v = *(const float4*)&AK[(b * DT + k) * DD + h * DHD + c4];
            Ks[c4 + 0][r] = v.x; Ks[c4 + 1][r] = v.y; Ks[c4 + 2][r] = v.z; Ks[c4 + 3][r] = v.w;
        }
        __syncthreads();
        float acc[4][4] = {};
#pragma unroll 16
        for (int cc = 0; cc < 64; cc++) {
            float4 a = *(const float4*)&Qs[cc][tx << 2];
            float4 bb = *(const float4*)&Ks[cc][ty << 2];
            FMA4x4(a, bb);
        }
#pragma unroll
        for (int i = 0; i < 4; i++)
#pragma unroll
            for (int j = 0; j < 4; j++) {
                int q = q0 + (tx << 2) + i;
                int k = k0 + (ty << 2) + j;
                if (k <= q && q - k < DWIN)
                    Sb[((b * DH + h) * DT + q) * DWIN + (k - q + DWIN - 1)] = acc[i][j] * 0.125f;
            }
        __syncthreads();
    }
}

// ---------------- attention: softmax over band (warp per row) ----------------
__global__ void attn_softmax_k(float* __restrict__ Sb) {
    int gw = (blockIdx.x * blockDim.x + threadIdx.x) >> 5;
    int lane = threadIdx.x & 31;
    if (gw >= DB * DH * DT) return;
    int q = gw % DT;
    int wlo = DWIN - 1 - q;
    if (wlo < 0) wlo = 0;
    float* row = Sb + gw * DWIN;
    float v[16];
    float m = -1e30f;
#pragma unroll
    for (int i = 0; i < 16; i++) {
        int w = lane + i * 32;
        v[i] = (w >= wlo) ? row[w] : -1e30f;
        m = fmaxf(m, v[i]);
    }
#pragma unroll
    for (int o = 16; o > 0; o >>= 1) m = fmaxf(m, __shfl_xor_sync(0xffffffffu, m, o));
    float sum = 0.0f;
#pragma unroll
    for (int i = 0; i < 16; i++) {
        int w = lane + i * 32;
        v[i] = (w >= wlo) ? __expf(v[i] - m) : 0.0f;
        sum += v[i];
    }
#pragma unroll
    for (int o = 16; o > 0; o >>= 1) sum += __shfl_xor_sync(0xffffffffu, sum, o);
    float inv = 1.0f / sum;
#pragma unroll
    for (int i = 0; i < 16; i++) {
        int w = lane + i * 32;
        if (w >= wlo) row[w] = v[i] * inv;
    }
}

// ---------------- attention: P @ V ----------------
__global__ void __launch_bounds__(256, 2) attn_pv_k(
    const float* __restrict__ Sb, const float* __restrict__ AV, float* __restrict__ AO) {
    __shared__ __align__(16) float Ps[64][68];   // Ps[k][q]
    __shared__ __align__(16) float Vs[64][68];   // Vs[k][c]
    const int q0 = blockIdx.x << 6;
    const int h = blockIdx.y, b = blockIdx.z;
    const int tid = threadIdx.x;
    const int tx = tid & 15, ty = tid >> 4;
    float acc[4][4] = {};
    int kLo = q0 - (DWIN - 1);
    if (kLo < 0) kLo = 0;
    kLo &= ~63;
    for (int k0 = kLo; k0 <= q0 + 63; k0 += 64) {
#pragma unroll
        for (int i = 0; i < 4; i++) {
            int idx = tid + (i << 8);
            int r = idx >> 4, c4 = (idx & 15) << 2;
            int k = k0 + r;
            float4 v = make_float4(0.f, 0.f, 0.f, 0.f);
            if (k < DT) v = *(const float4*)&AV[(b * DT + k) * DD + h * DHD + c4];
            *(float4*)&Vs[r][c4] = v;
        }
#pragma unroll
        for (int i = 0; i < 16; i++) {
            int lin = tid + (i << 8);              // 0..4095
            int qi = lin >> 6, kj = lin & 63;
            int q = q0 + qi, k = k0 + kj;
            float p = 0.0f;
            if (k <= q && q - k < DWIN)
                p = Sb[((b * DH + h) * DT + q) * DWIN + (k - q + DWIN - 1)];
            Ps[kj][qi] = p;
        }
        __syncthreads();
#pragma unroll 16
        for (int kk = 0; kk < 64; kk++) {
            float4 a = *(const float4*)&Ps[kk][tx << 2];
            float4 bb = *(const float4*)&Vs[kk][ty << 2];
            FMA4x4(a, bb);
        }
        __syncthreads();
    }
#pragma unroll
    for (int i = 0; i < 4; i++)
#pragma unroll
        for (int j = 0; j < 4; j++)
            AO[(b * DT + q0 + (tx << 2) + i) * DD + h * DHD + (ty << 2) + j] = acc[i][j];
}

// ---------------- host ----------------
extern "C" void kernel_launch(void* const* d_in, const int* in_sizes, int n_in,
                              void* d_out, int out_size) {
    const float* x      = (const float*)d_in[0];
    const float* meta   = (const float*)d_in[1];
    const float* lmm_w  = (const float*)d_in[2];
    const float* w_q    = (const float*)d_in[3];
    const float* w_k    = (const float*)d_in[4];
    const float* w_v    = (const float*)d_in[5];
    const float* w_lr   = (const float*)d_in[6];
    const float* swa_wq = (const float*)d_in[7];
    const float* swa_wk = (const float*)d_in[8];
    const float* swa_wv = (const float*)d_in[9];
    const float* swa_wo = (const float*)d_in[10];
    float* out = (float*)d_out;

    float *XM, *K, *V, *Q, *LR, *Z0, *X1, *Z1, *X2, *DY2, *DZ1, *DX1, *DZ0;
    float *Wn, *Y1, *Y2, *AQ, *AK, *AV, *AO, *Sb, *GP;
    cudaGetSymbolAddress((void**)&XM, g_XM);
    cudaGetSymbolAddress((void**)&K, g_K);
    cudaGetSymbolAddress((void**)&V, g_V);
    cudaGetSymbolAddress((void**)&Q, g_Q);
    cudaGetSymbolAddress((void**)&LR, g_LR);
    cudaGetSymbolAddress((void**)&Z0, g_Z0);
    cudaGetSymbolAddress((void**)&X1, g_X1);
    cudaGetSymbolAddress((void**)&Z1, g_Z1);
    cudaGetSymbolAddress((void**)&X2, g_X2);
    cudaGetSymbolAddress((void**)&DY2, g_DY2);
    cudaGetSymbolAddress((void**)&DZ1, g_DZ1);
    cudaGetSymbolAddress((void**)&DX1, g_DX1);
    cudaGetSymbolAddress((void**)&DZ0, g_DZ0);
    cudaGetSymbolAddress((void**)&Wn, g_Wn);
    cudaGetSymbolAddress((void**)&Y1, g_Y1);
    cudaGetSymbolAddress((void**)&Y2, g_Y2);
    cudaGetSymbolAddress((void**)&AQ, g_AQ);
    cudaGetSymbolAddress((void**)&AK, g_AK);
    cudaGetSymbolAddress((void**)&AV, g_AV);
    cudaGetSymbolAddress((void**)&AO, g_AO);
    cudaGetSymbolAddress((void**)&Sb, g_S);
    cudaGetSymbolAddress((void**)&GP, g_GP);

    const dim3 gG(DN / 64, DD / 128);           // 66 x 4 = 264 CTAs
    const dim3 gG3(DN / 64, DD / 128, 3);       // batched projections
    const dim3 gTN(DD / 64, DD / 128, NSPLIT);  // 8 x 4 x 8 = 256 CTAs
    const dim3 gAT(DT / 64, DH, DB);            // 33 x 8 x 2
    const int EW = (DN * DD + 255) / 256;

    // 1. concat meta + x
    build_xm_k<<<(DN * DD / 4 + 255) / 256, 256>>>(x, meta, XM);
    // 2. projections (batched: K, V, Q in one launch)
    gemm_nt3_k<<<gG3, 128>>>(XM, w_k, w_v, w_q, K, V, Q);
    lr_proj_k<<<(DN * 32 + 255) / 256, 256>>>(XM, w_lr, LR);
    // 3. LMM forward on keys (save z for backward)
    gemm_k<0, 1><<<gG, 128>>>(K, lmm_w, nullptr, Z0, X1);
    gemm_k<0, 1><<<gG, 128>>>(X1, lmm_w + DD * DD, nullptr, Z1, X2);
    // 4. backward
    grad_head_k<<<EW, 256>>>(X2, V, Z1, LR, DY2, DZ1);
    gemm_k<2, 0><<<gTN, 128>>>(DZ1, X1, nullptr, GP + NSPLIT * DD * DD, nullptr); // dW1
    gemm_k<1, 3><<<gG, 128>>>(DZ1, lmm_w + DD * DD, DY2, DX1, nullptr);           // dx1
    bwd_act0_k<<<EW, 256>>>(DX1, Z0, DZ0);
    gemm_k<2, 0><<<gTN, 128>>>(DZ0, K, nullptr, GP, nullptr);                     // dW0
    // 5. AdamW first step
    adamw_k<<<(NLAY * DD * DD + 255) / 256, 256>>>(lmm_w, Wn);
    // 6. retrieval with updated weights (Z0/Z1 reused as scratch)
    gemm_k<0, 1><<<gG, 128>>>(Q, Wn, nullptr, Z0, Y1);
    gemm_k<0, 1><<<gG, 128>>>(Y1, Wn + DD * DD, nullptr, Z1, Y2);
    // 7. sliding-window attention (batched QKV projection)
    gemm_nt3_k<<<gG3, 128>>>(Y2, swa_wq, swa_wk, swa_wv, AQ, AK, AV);
    attn_scores_k<<<gAT, 256>>>(AQ, AK, Sb);
    attn_softmax_k<<<(DB * DH * DT * 32 + 255) / 256, 256>>>(Sb);
    attn_pv_k<<<gAT, 256>>>(Sb, AV, AO);
    // 8. output projection, dropping meta rows
    gemm_k<0, 2><<<gG, 128>>>(AO, swa_wo, nullptr, nullptr, out);
}